// round 1
// baseline (speedup 1.0000x reference)
#include <cuda_runtime.h>

typedef unsigned long long ull;

#define WIDTHK  128
#define DD      8
#define NPTS    65536
#define TVALS   8
#define NSEG    7
#define TSTRIDE 4608          // floats per table: 128 rows * 36 floats
#define NTAB    63            // 7 segments * 9 unique times

// ---------------- packed f32x2 helpers (sm_103a) ----------------
__device__ __forceinline__ ull pk2(float a, float b){ ull r; asm("mov.b64 %0,{%1,%2};":"=l"(r):"f"(a),"f"(b)); return r; }
__device__ __forceinline__ void upk2(ull v, float&a, float&b){ asm("mov.b64 {%0,%1},%2;":"=f"(a),"=f"(b):"l"(v)); }
__device__ __forceinline__ ull ffma2(ull a, ull b, ull c){ ull d; asm("fma.rn.f32x2 %0,%1,%2,%3;":"=l"(d):"l"(a),"l"(b),"l"(c)); return d; }
__device__ __forceinline__ ull fmul2(ull a, ull b){ ull d; asm("mul.rn.f32x2 %0,%1,%2;":"=l"(d):"l"(a),"l"(b)); return d; }
__device__ __forceinline__ ull fadd2(ull a, ull b){ ull d; asm("add.rn.f32x2 %0,%1,%2;":"=l"(d):"l"(a),"l"(b)); return d; }
__device__ __forceinline__ float tanha(float x){ float r; asm("tanh.approx.f32 %0,%1;":"=f"(r):"f"(x)); return r; }

#define NEGONE2 0xBF800000BF800000ULL   // (-1.f, -1.f)
#define INVW2   0x3C0000003C000000ULL   // (1/128.f, 1/128.f)

// Hypernet tables. Per-k row (36 floats / 144B):
//  [0:16)  W[k][0..7] each duplicated  (8 x f32x2)
//  [16:32) U[k][0..7] duplicated       (8 x f32x2)
//  [32:36) B,B,c,c   where c = W_k . U_k
__device__ float g_tables[NTAB * TSTRIDE];

// ---------------- phase 1: hypernetwork ----------------
__global__ void hyper_kernel(const float* __restrict__ ts,
                             const float* __restrict__ w1, const float* __restrict__ b1,
                             const float* __restrict__ w2, const float* __restrict__ b2,
                             const float* __restrict__ w3, const float* __restrict__ b3)
{
    __shared__ float h1[64], h2[64];
    __shared__ float Wsh[1024], Ush[1024];

    int tbi  = blockIdx.x;
    int seg  = tbi / 9;
    int slot = tbi % 9;
    float t0 = ts[seg], t1 = ts[seg + 1];
    float dtv = (t1 - t0) * 0.25f;           // (t_next - t0)/NSUB, exact
    int j = slot >> 1;
    float t = t0;
    for (int i = 0; i < j; i++) t += dtv;    // sequential adds, matches scan carry
    if (slot & 1) t += dtv * 0.5f;

    int tid = threadIdx.x;
    if (tid < 64) h1[tid] = tanhf(w1[tid] * t + b1[tid]);
    __syncthreads();
    if (tid < 64) {
        float s = b2[tid];
        const float* r = w2 + tid * 64;
        for (int i = 0; i < 64; i++) s += r[i] * h1[i];
        h2[tid] = tanhf(s);
    }
    __syncthreads();

    float* tab = g_tables + tbi * TSTRIDE;

    for (int e = tid; e < 1024; e += blockDim.x) {
        const float* rw = w3 + e * 64;
        const float* ru = w3 + (1024 + e) * 64;
        const float* rg = w3 + (2048 + e) * 64;
        float sw = b3[e], su = b3[1024 + e], sg = b3[2048 + e];
        for (int i = 0; i < 64; i++) {
            float h = h2[i];
            sw += rw[i] * h; su += ru[i] * h; sg += rg[i] * h;
        }
        float u = su * (1.0f / (1.0f + expf(-sg)));
        int k = e >> 3, d = e & 7;
        tab[k * 36 + 2 * d]          = sw;
        tab[k * 36 + 2 * d + 1]      = sw;
        tab[k * 36 + 16 + 2 * d]     = u;
        tab[k * 36 + 16 + 2 * d + 1] = u;
        Wsh[e] = sw; Ush[e] = u;
    }
    if (tid < 128) {
        const float* r = w3 + (3072 + tid) * 64;
        float s = b3[3072 + tid];
        for (int i = 0; i < 64; i++) s += r[i] * h2[i];
        tab[tid * 36 + 32] = s;
        tab[tid * 36 + 33] = s;
    }
    __syncthreads();
    if (tid < 128) {
        float c = 0.f;
        for (int d = 0; d < 8; d++) c += Wsh[tid * 8 + d] * Ush[tid * 8 + d];
        tab[tid * 36 + 34] = c;
        tab[tid * 36 + 35] = c;
    }
}

// ---------------- phase 2: integrator ----------------
__device__ __forceinline__ void load_table(float* stab, int tbi)
{
    __syncthreads();   // previous RHS done reading stab
    const float4* src = (const float4*)(g_tables + tbi * TSTRIDE);
    float4* dst = (float4*)stab;
    #pragma unroll
    for (int i = 0; i < 9; i++)
        dst[threadIdx.x + i * 128] = src[threadIdx.x + i * 128];
    __syncthreads();
}

__device__ __forceinline__ void rhs_eval(const float* stab, const ull* y, ull* dz, ull& ldz)
{
    ull q = 0ull;
    #pragma unroll
    for (int j = 0; j < 8; j++) dz[j] = 0ull;

    #pragma unroll 2
    for (int k = 0; k < WIDTHK; k++) {
        const ulonglong2* row = (const ulonglong2*)(stab + k * 36);
        ulonglong2 w01 = row[0], w23 = row[1], w45 = row[2], w67 = row[3];
        ulonglong2 u01 = row[4], u23 = row[5], u45 = row[6], u67 = row[7];
        ulonglong2 bc  = row[8];              // (B,B | c,c)

        ull a0 = ffma2(w01.x, y[0], bc.x);    // even lanes + B
        ull a1 = fmul2(w01.y, y[1]);          // odd lanes
        a0 = ffma2(w23.x, y[2], a0);
        a1 = ffma2(w23.y, y[3], a1);
        a0 = ffma2(w45.x, y[4], a0);
        a1 = ffma2(w45.y, y[5], a1);
        a0 = ffma2(w67.x, y[6], a0);
        a1 = ffma2(w67.y, y[7], a1);
        ull s = fadd2(a0, a1);

        float fa, fb; upk2(s, fa, fb);
        ull h = pk2(tanha(fa), tanha(fb));

        ull sq = ffma2(h, h, (ull)NEGONE2);   // h^2 - 1
        q = ffma2(bc.y, sq, q);               // q += c*(h^2-1)  -> dlogp = q/128

        dz[0] = ffma2(h, u01.x, dz[0]); dz[1] = ffma2(h, u01.y, dz[1]);
        dz[2] = ffma2(h, u23.x, dz[2]); dz[3] = ffma2(h, u23.y, dz[3]);
        dz[4] = ffma2(h, u45.x, dz[4]); dz[5] = ffma2(h, u45.y, dz[5]);
        dz[6] = ffma2(h, u67.x, dz[6]); dz[7] = ffma2(h, u67.y, dz[7]);
    }
    #pragma unroll
    for (int j = 0; j < 8; j++) dz[j] = fmul2(dz[j], (ull)INVW2);
    ldz = fmul2(q, (ull)INVW2);
}

__global__ void __launch_bounds__(128)
cnf_main(const float* __restrict__ ts, const float* __restrict__ z0,
         const float* __restrict__ lp0, float* __restrict__ out)
{
    __shared__ __align__(16) float stab[TSTRIDE];

    int p  = blockIdx.x * 128 + threadIdx.x;   // 0 .. 32767
    int pA = p, pB = p + NPTS / 2;

    ull z[8], y[8], dz[8], acc[8];
    #pragma unroll
    for (int j = 0; j < 8; j++) z[j] = pk2(z0[pA * 8 + j], z0[pB * 8 + j]);
    ull lp = pk2(lp0[pA], lp0[pB]);

    const int ZT = TVALS * NPTS * DD;          // zt size in floats

    // slot 0 = initial state
    #pragma unroll
    for (int j = 0; j < 8; j++) {
        float a, b; upk2(z[j], a, b);
        out[pA * 8 + j] = a; out[pB * 8 + j] = b;
    }
    { float a, b; upk2(lp, a, b); out[ZT + pA] = a; out[ZT + pB] = b; }

    #pragma unroll 1
    for (int seg = 0; seg < NSEG; seg++) {
        float t0  = ts[seg];
        float dtv = (ts[seg + 1] - t0) * 0.25f;
        float dth = dtv * 0.5f;
        float dt6 = dtv / 6.0f;
        ull dth2 = pk2(dth, dth), dtf2 = pk2(dtv, dtv);
        ull dt62 = pk2(dt6, dt6), two2 = pk2(2.0f, 2.0f);

        #pragma unroll 1
        for (int sub = 0; sub < 4; sub++) {
            int tb = seg * 9 + 2 * sub;
            ull ldz, lacc;

            load_table(stab, tb);              // t
            rhs_eval(stab, z, dz, ldz);        // k1
            #pragma unroll
            for (int j = 0; j < 8; j++) { acc[j] = dz[j]; y[j] = ffma2(dth2, dz[j], z[j]); }
            lacc = ldz;

            load_table(stab, tb + 1);          // t + dt/2
            rhs_eval(stab, y, dz, ldz);        // k2
            #pragma unroll
            for (int j = 0; j < 8; j++) { acc[j] = ffma2(two2, dz[j], acc[j]); y[j] = ffma2(dth2, dz[j], z[j]); }
            lacc = ffma2(two2, ldz, lacc);

            rhs_eval(stab, y, dz, ldz);        // k3 (same table)
            #pragma unroll
            for (int j = 0; j < 8; j++) { acc[j] = ffma2(two2, dz[j], acc[j]); y[j] = ffma2(dtf2, dz[j], z[j]); }
            lacc = ffma2(two2, ldz, lacc);

            load_table(stab, tb + 2);          // t + dt
            rhs_eval(stab, y, dz, ldz);        // k4
            #pragma unroll
            for (int j = 0; j < 8; j++) { acc[j] = fadd2(acc[j], dz[j]); z[j] = ffma2(dt62, acc[j], z[j]); }
            lacc = fadd2(lacc, ldz);
            lp   = ffma2(dt62, lacc, lp);
        }

        int s1 = seg + 1;
        #pragma unroll
        for (int j = 0; j < 8; j++) {
            float a, b; upk2(z[j], a, b);
            out[(s1 * NPTS + pA) * 8 + j] = a;
            out[(s1 * NPTS + pB) * 8 + j] = b;
        }
        { float a, b; upk2(lp, a, b); out[ZT + s1 * NPTS + pA] = a; out[ZT + s1 * NPTS + pB] = b; }
    }
}

// ---------------- launch ----------------
extern "C" void kernel_launch(void* const* d_in, const int* in_sizes, int n_in,
                              void* d_out, int out_size)
{
    const float* ts  = (const float*)d_in[0];
    const float* z0  = (const float*)d_in[1];
    const float* lp0 = (const float*)d_in[2];
    const float* w1  = (const float*)d_in[3];
    const float* b1  = (const float*)d_in[4];
    const float* w2  = (const float*)d_in[5];
    const float* b2  = (const float*)d_in[6];
    const float* w3  = (const float*)d_in[7];
    const float* b3  = (const float*)d_in[8];
    float* out = (float*)d_out;

    hyper_kernel<<<NTAB, 256>>>(ts, w1, b1, w2, b2, w3, b3);
    cnf_main<<<NPTS / 2 / 128, 128>>>(ts, z0, lp0, out);
}